// round 9
// baseline (speedup 1.0000x reference)
#include <cuda_runtime.h>
#include <cuda_bf16.h>
#include <stdint.h>

// Problem constants (fixed by the reference)
#define MAXN 100000
#define MAXE 600000
#define F 128
#define BN_EPS 1e-5f

#define SCAN_BLK 4096
#define NBMAX 32

// ---------------- device scratch (no allocations allowed) ----------------
__device__ __align__(16) float g_h[(size_t)MAXN * F];     // h = x @ W
__device__ __align__(16) float g_agg[(size_t)MAXN * F];   // relu(agg)
__device__ __align__(16) __nv_bfloat16 g_xh[(size_t)MAXN * F];
__device__ __align__(16) __nv_bfloat16 g_xl[(size_t)MAXN * F];
__device__ __align__(16) __nv_bfloat16 g_wh[128 * 256];   // [k][c]: c<128 W, c>=128 W_res
__device__ __align__(16) __nv_bfloat16 g_wl[128 * 256];
__device__ int   g_deg[MAXN + 4];
__device__ int   g_off[MAXN + 4];
__device__ int   g_cur[MAXN];
__device__ int   g_src[MAXE];
__device__ float g_dinv[MAXN];
__device__ int   g_bsum[NBMAX];
__device__ float g_sum[F];
__device__ float g_sumsq[F];
__device__ float g_scale[F];
__device__ float g_shift[F];
__device__ int   g_is64;

// ---------------- helpers ----------------
__device__ __forceinline__ uint32_t smem_u32(const void* p) {
    uint32_t a;
    asm("{ .reg .u64 t; cvta.to.shared.u64 t, %1; cvt.u32.u64 %0, t; }"
        : "=r"(a) : "l"(p));
    return a;
}
__device__ __forceinline__ void split_bf16(float v, __nv_bfloat16& h, __nv_bfloat16& l) {
    h = __float2bfloat16(v);
    l = __float2bfloat16(v - __bfloat162float(h));
}
__device__ __forceinline__ uint32_t pack_bf162(__nv_bfloat16 a, __nv_bfloat16 b) {
    __nv_bfloat162 p = __halves2bfloat162(a, b);
    return *reinterpret_cast<uint32_t*>(&p);
}
__device__ __forceinline__ void cp16(uint32_t dst, const void* src, int srcsize) {
    asm volatile("cp.async.ca.shared.global [%0], [%1], 16, %2;"
        :: "r"(dst), "l"(src), "r"(srcsize) : "memory");
}
#define CP_COMMIT() asm volatile("cp.async.commit_group;" ::: "memory")
#define CP_WAIT(N)  asm volatile("cp.async.wait_group %0;" :: "n"(N) : "memory")

#define LDMX4(r0, r1, r2, r3, addr) \
    asm volatile("ldmatrix.sync.aligned.m8n8.x4.shared.b16 {%0,%1,%2,%3}, [%4];" \
        : "=r"(r0), "=r"(r1), "=r"(r2), "=r"(r3) : "r"(addr))
#define LDMX4T(r0, r1, r2, r3, addr) \
    asm volatile("ldmatrix.sync.aligned.m8n8.x4.trans.shared.b16 {%0,%1,%2,%3}, [%4];" \
        : "=r"(r0), "=r"(r1), "=r"(r2), "=r"(r3) : "r"(addr))
#define MMA16816(c, a, b0, b1) \
    asm volatile("mma.sync.aligned.m16n8k16.row.col.f32.bf16.bf16.f32 " \
        "{%0,%1,%2,%3}, {%4,%5,%6,%7}, {%8,%9}, {%0,%1,%2,%3};" \
        : "+f"((c)[0]), "+f"((c)[1]), "+f"((c)[2]), "+f"((c)[3]) \
        : "r"((a)[0]), "r"((a)[1]), "r"((a)[2]), "r"((a)[3]), "r"(b0), "r"(b1))

// ---------------- detect edge_index dtype (int64 vs silently-int32) -------
__global__ void detect_kernel(const void* ei, int n) {
    if (threadIdx.x == 0 && blockIdx.x == 0) {
        const long long* p = (const long long*)ei;
        int ok = 1;
#pragma unroll
        for (int i = 0; i < 16; i++) {
            long long v = p[i];
            if (v < 0 || v >= n) { ok = 0; break; }
        }
        g_is64 = ok;
    }
}

// ---------------- init ----------------
__global__ void init_kernel(int n) {
    int i = blockIdx.x * blockDim.x + threadIdx.x;
    if (i < n) g_deg[i] = 0;
    if (i < F) { g_sum[i] = 0.f; g_sumsq[i] = 0.f; }
}

// ---------------- hi/lo bf16 conversion: W+W_res (blocks 0..31), x (rest) --
__global__ void conv_kernel(const float* __restrict__ X,
                            const float* __restrict__ Wm,
                            const float* __restrict__ Wres, int n) {
    const int tid = threadIdx.x;
    const int bid = blockIdx.x;
    if (bid < 32) {
        int idx = bid * 256 + tid;        // 0..8191
        int is_res = idx >> 12;
        int r = idx & 4095;
        int k = r >> 5, c4 = r & 31;
        const float* src = is_res ? Wres : Wm;
        float4 v = *(const float4*)&src[k * 128 + c4 * 4];
        __nv_bfloat16 h0, l0, h1, l1, h2, l2, h3, l3;
        split_bf16(v.x, h0, l0); split_bf16(v.y, h1, l1);
        split_bf16(v.z, h2, l2); split_bf16(v.w, h3, l3);
        int dst = k * 256 + is_res * 128 + c4 * 4;
        *(uint2*)&g_wh[dst] = make_uint2(pack_bf162(h0, h1), pack_bf162(h2, h3));
        *(uint2*)&g_wl[dst] = make_uint2(pack_bf162(l0, l1), pack_bf162(l2, l3));
    } else {
        int idx = (bid - 32) * 256 + tid;
        if (idx < n * 32) {
            float4 v = ((const float4*)X)[idx];
            __nv_bfloat16 h0, l0, h1, l1, h2, l2, h3, l3;
            split_bf16(v.x, h0, l0); split_bf16(v.y, h1, l1);
            split_bf16(v.z, h2, l2); split_bf16(v.w, h3, l3);
            *(uint2*)&g_xh[(size_t)idx * 4] =
                make_uint2(pack_bf162(h0, h1), pack_bf162(h2, h3));
            *(uint2*)&g_xl[(size_t)idx * 4] =
                make_uint2(pack_bf162(l0, l1), pack_bf162(l2, l3));
        }
    }
}

// ---------------- degree histogram over destination (col) ----------------
__global__ void deg_kernel(const void* __restrict__ ei, int E) {
    int e = blockIdx.x * blockDim.x + threadIdx.x;
    if (e < E) {
        int c;
        if (g_is64) c = (int)((const long long*)ei)[E + e];
        else        c = ((const int*)ei)[E + e];
        atomicAdd(&g_deg[c], 1);
    }
}

// ---------------- 3-phase scan ----------------
__global__ void scan1_kernel(int n) {
    __shared__ int wsum[32];
    const int t = threadIdx.x;
    const int lane = t & 31;
    const int w = t >> 5;
    const int idx = blockIdx.x * SCAN_BLK + t * 4;

    int d0 = 0, d1 = 0, d2 = 0, d3 = 0;
    if (idx + 3 < n) {
        int4 dd = *(const int4*)&g_deg[idx];
        d0 = dd.x; d1 = dd.y; d2 = dd.z; d3 = dd.w;
    } else {
        if (idx + 0 < n) d0 = g_deg[idx + 0];
        if (idx + 1 < n) d1 = g_deg[idx + 1];
        if (idx + 2 < n) d2 = g_deg[idx + 2];
        if (idx + 3 < n) d3 = g_deg[idx + 3];
    }
    int s = d0 + d1 + d2 + d3;
    int v = s;
#pragma unroll
    for (int o = 1; o < 32; o <<= 1) {
        int a = __shfl_up_sync(0xffffffffu, v, o);
        if (lane >= o) v += a;
    }
    if (lane == 31) wsum[w] = v;
    __syncthreads();
    if (w == 0) {
        int sv = wsum[lane];
#pragma unroll
        for (int o = 1; o < 32; o <<= 1) {
            int a = __shfl_up_sync(0xffffffffu, sv, o);
            if (lane >= o) sv += a;
        }
        wsum[lane] = sv;
    }
    __syncthreads();
    int excl = (w ? wsum[w - 1] : 0) + v - s;

    if (idx + 3 < n) {
        int4 oo = make_int4(excl, excl + d0, excl + d0 + d1, excl + d0 + d1 + d2);
        *(int4*)&g_off[idx] = oo;
        g_dinv[idx + 0] = rsqrtf((float)(d0 + 1));
        g_dinv[idx + 1] = rsqrtf((float)(d1 + 1));
        g_dinv[idx + 2] = rsqrtf((float)(d2 + 1));
        g_dinv[idx + 3] = rsqrtf((float)(d3 + 1));
    } else {
        int e = excl;
        if (idx + 0 < n) { g_off[idx + 0] = e; g_dinv[idx + 0] = rsqrtf((float)(d0 + 1)); e += d0; }
        if (idx + 1 < n) { g_off[idx + 1] = e; g_dinv[idx + 1] = rsqrtf((float)(d1 + 1)); e += d1; }
        if (idx + 2 < n) { g_off[idx + 2] = e; g_dinv[idx + 2] = rsqrtf((float)(d2 + 1)); e += d2; }
        if (idx + 3 < n) { g_off[idx + 3] = e; g_dinv[idx + 3] = rsqrtf((float)(d3 + 1)); }
    }
    if (t == 0) g_bsum[blockIdx.x] = wsum[31];
}

__global__ void scan2_kernel(int nb) {
    int lane = threadIdx.x;
    int v = (lane < nb) ? g_bsum[lane] : 0;
    int orig = v;
#pragma unroll
    for (int o = 1; o < 32; o <<= 1) {
        int a = __shfl_up_sync(0xffffffffu, v, o);
        if (lane >= o) v += a;
    }
    if (lane < nb) g_bsum[lane] = v - orig;
}

__global__ void scan3_kernel(int n) {
    int i = blockIdx.x * blockDim.x + threadIdx.x;
    if (i < n) {
        int o = g_off[i] + g_bsum[i >> 12];
        g_off[i] = o;
        g_cur[i] = o;
    }
}

// ---------------- CSR fill ----------------
__global__ void fill_kernel(const void* __restrict__ ei, int E) {
    int e = blockIdx.x * blockDim.x + threadIdx.x;
    if (e < E) {
        int r, c;
        if (g_is64) {
            r = (int)((const long long*)ei)[e];
            c = (int)((const long long*)ei)[E + e];
        } else {
            r = ((const int*)ei)[e];
            c = ((const int*)ei)[E + e];
        }
        int p = atomicAdd(&g_cur[c], 1);
        g_src[p] = r;
    }
}

// ---------------- mma.sync bf16 dual GEMM, cp.async double-buffered -------
// Block: 256 threads (2x4 warps), tile 64 rows x 256 cols (W | W_res).
// Sources are pre-split bf16 hi/lo arrays. K chunked by 16, 2-stage pipeline.
// 3-term product: ah*bh + ah*bl + al*bh  (rel err ~5e-6).
#define GM 64
#define LDA2 24      // A smem stride (bf16): 48 B, conflict-free ldmatrix
#define LDB2 280     // B smem stride (bf16): 560 B, odd 16B-phase

__global__ void __launch_bounds__(256)
gemm_mma_kernel(const float* __restrict__ b_res, float* __restrict__ out, int n) {
    __shared__ __align__(16) __nv_bfloat16 sA[2][2][GM * LDA2];   // 12 KB
    __shared__ __align__(16) __nv_bfloat16 sB[2][2][16 * LDB2];   // 35 KB

    const int tid = threadIdx.x;
    const int lane = tid & 31;
    const int wid = tid >> 5;
    const int warpM = wid >> 2;
    const int warpN = wid & 3;
    const int block_row = blockIdx.x * GM;

    float acc[2][8][4];
#pragma unroll
    for (int i = 0; i < 2; i++)
#pragma unroll
        for (int j = 0; j < 8; j++)
#pragma unroll
            for (int q = 0; q < 4; q++) acc[i][j][q] = 0.f;

    uint32_t uA[2][2], uB[2][2];
#pragma unroll
    for (int s = 0; s < 2; s++) {
#pragma unroll
        for (int p = 0; p < 2; p++) {
            uA[s][p] = smem_u32(sA[s][p]);
            uB[s][p] = smem_u32(sB[s][p]);
        }
    }

    // ---- cp.async roles ----
    // A: 256 segs (64 rows x 2 x hi/lo), 1 per thread
    const int apart = tid >> 7;
    const int arow = (tid & 127) >> 1;
    const int aseg = tid & 1;
    const int agr = block_row + arow;
    const __nv_bfloat16* asrc =
        (apart ? g_xl : g_xh) + (size_t)(agr < n ? agr : 0) * F + aseg * 8;
    const int asz = (agr < n) ? 16 : 0;
    const uint32_t adst = (uint32_t)(arow * LDA2 + aseg * 8) * 2;

    // B: 1024 segs (16 k x 32 x hi/lo), 4 per thread
    const __nv_bfloat16* bsrc[4];
    uint32_t bdst[4];
    int bpart[4];
#pragma unroll
    for (int q = 0; q < 4; q++) {
        int segid = q * 256 + tid;
        bpart[q] = segid >> 9;
        int rem = segid & 511;
        int kr = rem >> 5;
        int sg = rem & 31;
        bsrc[q] = (bpart[q] ? g_wl : g_wh) + kr * 256 + sg * 8;
        bdst[q] = (uint32_t)(kr * LDB2 + sg * 8) * 2;
    }

    // ldmatrix offsets
    uint32_t a_off[2];
#pragma unroll
    for (int mf = 0; mf < 2; mf++)
        a_off[mf] = (uint32_t)((warpM * 32 + mf * 16 + (lane & 15)) * (LDA2 * 2)
                  + (lane >> 4) * 16);
    uint32_t b_off[4];
#pragma unroll
    for (int nf2 = 0; nf2 < 4; nf2++)
        b_off[nf2] = (uint32_t)((lane & 15) * (LDB2 * 2)
                   + (warpN * 64 + nf2 * 16 + (lane >> 4) * 8) * 2);

#define ISSUE(st, kc) do { \
        cp16(uA[st][apart] + adst, asrc + (kc), asz); \
        _Pragma("unroll") \
        for (int q = 0; q < 4; q++) \
            cp16(uB[st][bpart[q]] + bdst[q], bsrc[q] + (size_t)(kc) * 256, 16); \
        CP_COMMIT(); \
    } while (0)

    ISSUE(0, 0);

#pragma unroll
    for (int c = 0; c < 8; c++) {
        if (c < 7) {
            ISSUE((c + 1) & 1, (c + 1) * 16);
            CP_WAIT(1);
        } else {
            CP_WAIT(0);
        }
        __syncthreads();
        const int st = c & 1;

        uint32_t ah[2][4], al[2][4];
#pragma unroll
        for (int mf = 0; mf < 2; mf++) {
            LDMX4(ah[mf][0], ah[mf][1], ah[mf][2], ah[mf][3], uA[st][0] + a_off[mf]);
            LDMX4(al[mf][0], al[mf][1], al[mf][2], al[mf][3], uA[st][1] + a_off[mf]);
        }
#pragma unroll
        for (int nf2 = 0; nf2 < 4; nf2++) {
            uint32_t bh[4], bl[4];
            LDMX4T(bh[0], bh[1], bh[2], bh[3], uB[st][0] + b_off[nf2]);
            LDMX4T(bl[0], bl[1], bl[2], bl[3], uB[st][1] + b_off[nf2]);
#pragma unroll
            for (int half = 0; half < 2; half++) {
                int nf = nf2 * 2 + half;
#pragma unroll
                for (int mf = 0; mf < 2; mf++) {
                    MMA16816(acc[mf][nf], ah[mf], bh[half * 2], bh[half * 2 + 1]);
                    MMA16816(acc[mf][nf], ah[mf], bl[half * 2], bl[half * 2 + 1]);
                    MMA16816(acc[mf][nf], al[mf], bh[half * 2], bh[half * 2 + 1]);
                }
            }
        }
        __syncthreads();
    }
#undef ISSUE

    // ---- epilogue: direct register stores ----
#pragma unroll
    for (int mf = 0; mf < 2; mf++) {
        int gr0 = block_row + warpM * 32 + mf * 16 + (lane >> 2);
#pragma unroll
        for (int nf = 0; nf < 8; nf++) {
            int cg = warpN * 64 + nf * 8 + (lane & 3) * 2;
            float bias0 = 0.f, bias1 = 0.f;
            float* dst;
            int col;
            if (cg < 128) {
                dst = g_h; col = cg;
            } else {
                dst = out; col = cg - 128;
                bias0 = b_res[col];
                bias1 = b_res[col + 1];
            }
            if (gr0 < n) {
                float2 o = make_float2(acc[mf][nf][0] + bias0,
                                       acc[mf][nf][1] + bias1);
                *(float2*)&dst[(size_t)gr0 * F + col] = o;
            }
            if (gr0 + 8 < n) {
                float2 o = make_float2(acc[mf][nf][2] + bias0,
                                       acc[mf][nf][3] + bias1);
                *(float2*)&dst[(size_t)(gr0 + 8) * F + col] = o;
            }
        }
    }
}

// ---------------- aggregate (gather) + self-loop + bias + ReLU + BN stats --
__global__ void aggregate_kernel(const float* __restrict__ b, int n) {
    __shared__ float bsum[F];
    __shared__ float bsq[F];
    const int t = threadIdx.x;
    if (t < F) { bsum[t] = 0.f; bsq[t] = 0.f; }
    __syncthreads();

    const int node = (blockIdx.x * blockDim.x + t) >> 5;
    const int lane = t & 31;

    if (node < n) {
        const float4* h4 = (const float4*)g_h;
        float dc = g_dinv[node];
        float dc2 = dc * dc;
        int j = g_off[node];
        int end = j + g_deg[node];

        float4 acc = h4[(size_t)node * 32 + lane];
        float4 bv = ((const float4*)b)[lane];
        acc.x = fmaf(acc.x, dc2, bv.x);
        acc.y = fmaf(acc.y, dc2, bv.y);
        acc.z = fmaf(acc.z, dc2, bv.z);
        acc.w = fmaf(acc.w, dc2, bv.w);

        // 2-way unrolled: two independent load chains per iteration
        for (; j + 1 < end; j += 2) {
            int r0 = g_src[j];
            int r1 = g_src[j + 1];
            float n0 = dc * g_dinv[r0];
            float n1 = dc * g_dinv[r1];
            float4 v0 = h4[(size_t)r0 * 32 + lane];
            float4 v1 = h4[(size_t)r1 * 32 + lane];
            acc.x = fmaf(v0.x, n0, acc.x);
            acc.y = fmaf(v0.y, n0, acc.y);
            acc.z = fmaf(v0.z, n0, acc.z);
            acc.w = fmaf(v0.w, n0, acc.w);
            acc.x = fmaf(v1.x, n1, acc.x);
            acc.y = fmaf(v1.y, n1, acc.y);
            acc.z = fmaf(v1.z, n1, acc.z);
            acc.w = fmaf(v1.w, n1, acc.w);
        }
        if (j < end) {
            int r = g_src[j];
            float nrm = dc * g_dinv[r];
            float4 v = h4[(size_t)r * 32 + lane];
            acc.x = fmaf(v.x, nrm, acc.x);
            acc.y = fmaf(v.y, nrm, acc.y);
            acc.z = fmaf(v.z, nrm, acc.z);
            acc.w = fmaf(v.w, nrm, acc.w);
        }
        acc.x = fmaxf(acc.x, 0.f);
        acc.y = fmaxf(acc.y, 0.f);
        acc.z = fmaxf(acc.z, 0.f);
        acc.w = fmaxf(acc.w, 0.f);
        ((float4*)g_agg)[(size_t)node * 32 + lane] = acc;

        int f0 = lane * 4;
        atomicAdd(&bsum[f0 + 0], acc.x);
        atomicAdd(&bsum[f0 + 1], acc.y);
        atomicAdd(&bsum[f0 + 2], acc.z);
        atomicAdd(&bsum[f0 + 3], acc.w);
        atomicAdd(&bsq[f0 + 0], acc.x * acc.x);
        atomicAdd(&bsq[f0 + 1], acc.y * acc.y);
        atomicAdd(&bsq[f0 + 2], acc.z * acc.z);
        atomicAdd(&bsq[f0 + 3], acc.w * acc.w);
    }
    __syncthreads();
    if (t < F) {
        atomicAdd(&g_sum[t], bsum[t]);
        atomicAdd(&g_sumsq[t], bsq[t]);
    }
}

// ---------------- fold mean/var/gamma/beta into scale/shift ----------------
__global__ void finalize_stats_kernel(const float* __restrict__ gamma,
                                      const float* __restrict__ beta, int n) {
    int f = threadIdx.x;
    if (f < F) {
        float inv_n = 1.f / (float)n;
        float mean = g_sum[f] * inv_n;
        float var = g_sumsq[f] * inv_n - mean * mean;
        float istd = rsqrtf(var + BN_EPS);
        float sc = gamma[f] * istd;
        g_scale[f] = sc;
        g_shift[f] = beta[f] - mean * sc;
    }
}

// ---------------- final: out += r*scale + shift (out holds res+b_res) -----
__global__ void final_kernel(float* __restrict__ out, int n) {
    int tid = blockIdx.x * blockDim.x + threadIdx.x;
    if (tid >= n * (F / 4)) return;
    int s = tid & 31;
    float4 a = ((const float4*)g_agg)[tid];
    float4 sc = ((const float4*)g_scale)[s];
    float4 sh = ((const float4*)g_shift)[s];
    float4 o = ((float4*)out)[tid];
    o.x += a.x * sc.x + sh.x;
    o.y += a.y * sc.y + sh.y;
    o.z += a.z * sc.z + sh.z;
    o.w += a.w * sc.w + sh.w;
    ((float4*)out)[tid] = o;
}

// ---------------- launch ----------------------------------------------------
static cudaStream_t s_csr = nullptr;
static cudaEvent_t s_evF = nullptr, s_evJ = nullptr;

extern "C" void kernel_launch(void* const* d_in, const int* in_sizes, int n_in,
                              void* d_out, int out_size) {
    const float* x        = (const float*)d_in[0];
    const void*  ei       = d_in[1];
    const float* W        = (const float*)d_in[2];
    const float* b        = (const float*)d_in[3];
    const float* gamma    = (const float*)d_in[4];
    const float* beta     = (const float*)d_in[5];
    const float* W_res    = (const float*)d_in[6];
    const float* b_res    = (const float*)d_in[7];
    float* out            = (float*)d_out;

    const int n = in_sizes[0] / F;
    const int E = in_sizes[1] / 2;
    const int nb = (n + SCAN_BLK - 1) / SCAN_BLK;

    if (s_csr == nullptr) {   // first (non-captured) call only; reused thereafter
        cudaStreamCreateWithFlags(&s_csr, cudaStreamNonBlocking);
        cudaEventCreateWithFlags(&s_evF, cudaEventDisableTiming);
        cudaEventCreateWithFlags(&s_evJ, cudaEventDisableTiming);
    }

    const int T = 256;
    detect_kernel<<<1, 32>>>(ei, n);                            // 1
    init_kernel<<<(n + T - 1) / T, T>>>(n);                     // 2
    conv_kernel<<<32 + (n * 32 + T - 1) / T, T>>>(x, W, W_res, n);  // 3
    gemm_mma_kernel<<<(n + GM - 1) / GM, 256>>>(b_res, out, n); // 4 (profiled)

    // CSR build forked onto a second stream, overlapping conv+gemm
    cudaEventRecord(s_evF, 0);
    cudaStreamWaitEvent(s_csr, s_evF, 0);
    deg_kernel<<<(E + T - 1) / T, T, 0, s_csr>>>(ei, E);
    scan1_kernel<<<nb, 1024, 0, s_csr>>>(n);
    scan2_kernel<<<1, 32, 0, s_csr>>>(nb);
    scan3_kernel<<<(n + T - 1) / T, T, 0, s_csr>>>(n);
    fill_kernel<<<(E + T - 1) / T, T, 0, s_csr>>>(ei, E);
    cudaEventRecord(s_evJ, s_csr);
    cudaStreamWaitEvent(0, s_evJ, 0);

    {
        long long work = (long long)n * 32;
        aggregate_kernel<<<(int)((work + T - 1) / T), T>>>(b, n);
    }
    finalize_stats_kernel<<<1, F>>>(gamma, beta, n);
    {
        int work = n * (F / 4);
        final_kernel<<<(work + T - 1) / T, T>>>(out, n);
    }
}

// round 10
// speedup vs baseline: 1.0943x; 1.0943x over previous
#include <cuda_runtime.h>
#include <cuda_bf16.h>
#include <stdint.h>

// Problem constants (fixed by the reference)
#define MAXN 100000
#define MAXE 600000
#define F 128
#define BN_EPS 1e-5f

#define SCAN_BLK 4096
#define NBMAX 32

// ---------------- device scratch (no allocations allowed) ----------------
__device__ __align__(16) float g_h[(size_t)MAXN * F];     // h = x @ W
__device__ __align__(16) float g_agg[(size_t)MAXN * F];   // relu(agg)
__device__ __align__(16) __nv_bfloat16 g_xh[(size_t)MAXN * F];
__device__ __align__(16) __nv_bfloat16 g_xl[(size_t)MAXN * F];
__device__ __align__(16) __nv_bfloat16 g_wh[128 * 256];   // [k][c]: c<128 W, c>=128 W_res
__device__ __align__(16) __nv_bfloat16 g_wl[128 * 256];
__device__ int   g_deg[MAXN + 4];
__device__ int   g_off[MAXN + 4];
__device__ int   g_cur[MAXN];
__device__ int   g_src[MAXE];
__device__ float g_dinv[MAXN];
__device__ int   g_bsum[NBMAX];
__device__ float g_sum[F];
__device__ float g_sumsq[F];
__device__ float g_scale[F];
__device__ float g_shift[F];
__device__ int   g_is64;

// ---------------- helpers ----------------
__device__ __forceinline__ uint32_t smem_u32(const void* p) {
    uint32_t a;
    asm("{ .reg .u64 t; cvta.to.shared.u64 t, %1; cvt.u32.u64 %0, t; }"
        : "=r"(a) : "l"(p));
    return a;
}
__device__ __forceinline__ void split_bf16(float v, __nv_bfloat16& h, __nv_bfloat16& l) {
    h = __float2bfloat16(v);
    l = __float2bfloat16(v - __bfloat162float(h));
}
__device__ __forceinline__ uint32_t pack_bf162(__nv_bfloat16 a, __nv_bfloat16 b) {
    __nv_bfloat162 p = __halves2bfloat162(a, b);
    return *reinterpret_cast<uint32_t*>(&p);
}
__device__ __forceinline__ void cp16(uint32_t dst, const void* src, int srcsize) {
    asm volatile("cp.async.ca.shared.global [%0], [%1], 16, %2;"
        :: "r"(dst), "l"(src), "r"(srcsize) : "memory");
}
#define CP_COMMIT() asm volatile("cp.async.commit_group;" ::: "memory")
#define CP_WAIT(N)  asm volatile("cp.async.wait_group %0;" :: "n"(N) : "memory")

#define LDMX4(r0, r1, r2, r3, addr) \
    asm volatile("ldmatrix.sync.aligned.m8n8.x4.shared.b16 {%0,%1,%2,%3}, [%4];" \
        : "=r"(r0), "=r"(r1), "=r"(r2), "=r"(r3) : "r"(addr))
#define LDMX4T(r0, r1, r2, r3, addr) \
    asm volatile("ldmatrix.sync.aligned.m8n8.x4.trans.shared.b16 {%0,%1,%2,%3}, [%4];" \
        : "=r"(r0), "=r"(r1), "=r"(r2), "=r"(r3) : "r"(addr))
#define MMA16816(c, a, b0, b1) \
    asm volatile("mma.sync.aligned.m16n8k16.row.col.f32.bf16.bf16.f32 " \
        "{%0,%1,%2,%3}, {%4,%5,%6,%7}, {%8,%9}, {%0,%1,%2,%3};" \
        : "+f"((c)[0]), "+f"((c)[1]), "+f"((c)[2]), "+f"((c)[3]) \
        : "r"((a)[0]), "r"((a)[1]), "r"((a)[2]), "r"((a)[3]), "r"(b0), "r"(b1))

// ---------------- detect edge_index dtype (int64 vs silently-int32) -------
__global__ void detect_kernel(const void* ei, int n) {
    if (threadIdx.x == 0 && blockIdx.x == 0) {
        const long long* p = (const long long*)ei;
        int ok = 1;
#pragma unroll
        for (int i = 0; i < 16; i++) {
            long long v = p[i];
            if (v < 0 || v >= n) { ok = 0; break; }
        }
        g_is64 = ok;
    }
}

// ---------------- init ----------------
__global__ void init_kernel(int n) {
    int i = blockIdx.x * blockDim.x + threadIdx.x;
    if (i < n) g_deg[i] = 0;
    if (i < F) { g_sum[i] = 0.f; g_sumsq[i] = 0.f; }
}

// ---------------- hi/lo bf16 conversion: W+W_res (blocks 0..31), x (rest) --
__global__ void conv_kernel(const float* __restrict__ X,
                            const float* __restrict__ Wm,
                            const float* __restrict__ Wres, int n) {
    const int tid = threadIdx.x;
    const int bid = blockIdx.x;
    if (bid < 32) {
        int idx = bid * 256 + tid;        // 0..8191
        int is_res = idx >> 12;
        int r = idx & 4095;
        int k = r >> 5, c4 = r & 31;
        const float* src = is_res ? Wres : Wm;
        float4 v = *(const float4*)&src[k * 128 + c4 * 4];
        __nv_bfloat16 h0, l0, h1, l1, h2, l2, h3, l3;
        split_bf16(v.x, h0, l0); split_bf16(v.y, h1, l1);
        split_bf16(v.z, h2, l2); split_bf16(v.w, h3, l3);
        int dst = k * 256 + is_res * 128 + c4 * 4;
        *(uint2*)&g_wh[dst] = make_uint2(pack_bf162(h0, h1), pack_bf162(h2, h3));
        *(uint2*)&g_wl[dst] = make_uint2(pack_bf162(l0, l1), pack_bf162(l2, l3));
    } else {
        int idx = (bid - 32) * 256 + tid;
        if (idx < n * 32) {
            float4 v = ((const float4*)X)[idx];
            __nv_bfloat16 h0, l0, h1, l1, h2, l2, h3, l3;
            split_bf16(v.x, h0, l0); split_bf16(v.y, h1, l1);
            split_bf16(v.z, h2, l2); split_bf16(v.w, h3, l3);
            *(uint2*)&g_xh[(size_t)idx * 4] =
                make_uint2(pack_bf162(h0, h1), pack_bf162(h2, h3));
            *(uint2*)&g_xl[(size_t)idx * 4] =
                make_uint2(pack_bf162(l0, l1), pack_bf162(l2, l3));
        }
    }
}

// ---------------- degree histogram over destination (col) ----------------
__global__ void deg_kernel(const void* __restrict__ ei, int E) {
    int e = blockIdx.x * blockDim.x + threadIdx.x;
    if (e < E) {
        int c;
        if (g_is64) c = (int)((const long long*)ei)[E + e];
        else        c = ((const int*)ei)[E + e];
        atomicAdd(&g_deg[c], 1);
    }
}

// ---------------- 3-phase scan ----------------
__global__ void scan1_kernel(int n) {
    __shared__ int wsum[32];
    const int t = threadIdx.x;
    const int lane = t & 31;
    const int w = t >> 5;
    const int idx = blockIdx.x * SCAN_BLK + t * 4;

    int d0 = 0, d1 = 0, d2 = 0, d3 = 0;
    if (idx + 3 < n) {
        int4 dd = *(const int4*)&g_deg[idx];
        d0 = dd.x; d1 = dd.y; d2 = dd.z; d3 = dd.w;
    } else {
        if (idx + 0 < n) d0 = g_deg[idx + 0];
        if (idx + 1 < n) d1 = g_deg[idx + 1];
        if (idx + 2 < n) d2 = g_deg[idx + 2];
        if (idx + 3 < n) d3 = g_deg[idx + 3];
    }
    int s = d0 + d1 + d2 + d3;
    int v = s;
#pragma unroll
    for (int o = 1; o < 32; o <<= 1) {
        int a = __shfl_up_sync(0xffffffffu, v, o);
        if (lane >= o) v += a;
    }
    if (lane == 31) wsum[w] = v;
    __syncthreads();
    if (w == 0) {
        int sv = wsum[lane];
#pragma unroll
        for (int o = 1; o < 32; o <<= 1) {
            int a = __shfl_up_sync(0xffffffffu, sv, o);
            if (lane >= o) sv += a;
        }
        wsum[lane] = sv;
    }
    __syncthreads();
    int excl = (w ? wsum[w - 1] : 0) + v - s;

    if (idx + 3 < n) {
        int4 oo = make_int4(excl, excl + d0, excl + d0 + d1, excl + d0 + d1 + d2);
        *(int4*)&g_off[idx] = oo;
        g_dinv[idx + 0] = rsqrtf((float)(d0 + 1));
        g_dinv[idx + 1] = rsqrtf((float)(d1 + 1));
        g_dinv[idx + 2] = rsqrtf((float)(d2 + 1));
        g_dinv[idx + 3] = rsqrtf((float)(d3 + 1));
    } else {
        int e = excl;
        if (idx + 0 < n) { g_off[idx + 0] = e; g_dinv[idx + 0] = rsqrtf((float)(d0 + 1)); e += d0; }
        if (idx + 1 < n) { g_off[idx + 1] = e; g_dinv[idx + 1] = rsqrtf((float)(d1 + 1)); e += d1; }
        if (idx + 2 < n) { g_off[idx + 2] = e; g_dinv[idx + 2] = rsqrtf((float)(d2 + 1)); e += d2; }
        if (idx + 3 < n) { g_off[idx + 3] = e; g_dinv[idx + 3] = rsqrtf((float)(d3 + 1)); }
    }
    if (t == 0) g_bsum[blockIdx.x] = wsum[31];
}

__global__ void scan2_kernel(int nb) {
    int lane = threadIdx.x;
    int v = (lane < nb) ? g_bsum[lane] : 0;
    int orig = v;
#pragma unroll
    for (int o = 1; o < 32; o <<= 1) {
        int a = __shfl_up_sync(0xffffffffu, v, o);
        if (lane >= o) v += a;
    }
    if (lane < nb) g_bsum[lane] = v - orig;
}

__global__ void scan3_kernel(int n) {
    int i = blockIdx.x * blockDim.x + threadIdx.x;
    if (i < n) {
        int o = g_off[i] + g_bsum[i >> 12];
        g_off[i] = o;
        g_cur[i] = o;
    }
}

// ---------------- CSR fill ----------------
__global__ void fill_kernel(const void* __restrict__ ei, int E) {
    int e = blockIdx.x * blockDim.x + threadIdx.x;
    if (e < E) {
        int r, c;
        if (g_is64) {
            r = (int)((const long long*)ei)[e];
            c = (int)((const long long*)ei)[E + e];
        } else {
            r = ((const int*)ei)[e];
            c = ((const int*)ei)[E + e];
        }
        int p = atomicAdd(&g_cur[c], 1);
        g_src[p] = r;
    }
}

// ---------------- mma.sync bf16 dual GEMM, cp.async double-buffered -------
// Block: 256 threads (2x4 warps), tile 64 rows x 256 cols (W | W_res).
// Pre-split bf16 hi/lo sources; K chunked by 16, 2-stage cp.async pipeline.
// 3-term product: ah*bh + ah*bl + al*bh  (rel err ~5e-6).
// __launch_bounds__(256,2): cap regs at 128 -> 2 CTAs/SM (was 162 regs, occ 11.9%).
#define GM 64
#define LDA2 24      // A smem stride (bf16)
#define LDB2 280     // B smem stride (bf16)

__global__ void __launch_bounds__(256, 2)
gemm_mma_kernel(const float* __restrict__ b_res, float* __restrict__ out, int n) {
    __shared__ __align__(16) __nv_bfloat16 sA[2][2][GM * LDA2];   // 12 KB
    __shared__ __align__(16) __nv_bfloat16 sB[2][2][16 * LDB2];   // 35 KB

    const int tid = threadIdx.x;
    const int lane = tid & 31;
    const int wid = tid >> 5;
    const int warpM = wid >> 2;
    const int warpN = wid & 3;
    const int block_row = blockIdx.x * GM;

    float acc[2][8][4];
#pragma unroll
    for (int i = 0; i < 2; i++)
#pragma unroll
        for (int j = 0; j < 8; j++)
#pragma unroll
            for (int q = 0; q < 4; q++) acc[i][j][q] = 0.f;

    uint32_t uA[2][2], uB[2][2];
#pragma unroll
    for (int s = 0; s < 2; s++) {
#pragma unroll
        for (int p = 0; p < 2; p++) {
            uA[s][p] = smem_u32(sA[s][p]);
            uB[s][p] = smem_u32(sB[s][p]);
        }
    }

    // ---- cp.async roles ----
    const int apart = tid >> 7;
    const int arow = (tid & 127) >> 1;
    const int aseg = tid & 1;
    const int agr = block_row + arow;
    const __nv_bfloat16* asrc =
        (apart ? g_xl : g_xh) + (size_t)(agr < n ? agr : 0) * F + aseg * 8;
    const int asz = (agr < n) ? 16 : 0;
    const uint32_t adst = (uint32_t)(arow * LDA2 + aseg * 8) * 2;

    const __nv_bfloat16* bsrc[4];
    uint32_t bdst[4];
    int bpart[4];
#pragma unroll
    for (int q = 0; q < 4; q++) {
        int segid = q * 256 + tid;
        bpart[q] = segid >> 9;
        int rem = segid & 511;
        int kr = rem >> 5;
        int sg = rem & 31;
        bsrc[q] = (bpart[q] ? g_wl : g_wh) + kr * 256 + sg * 8;
        bdst[q] = (uint32_t)(kr * LDB2 + sg * 8) * 2;
    }

    uint32_t a_off[2];
#pragma unroll
    for (int mf = 0; mf < 2; mf++)
        a_off[mf] = (uint32_t)((warpM * 32 + mf * 16 + (lane & 15)) * (LDA2 * 2)
                  + (lane >> 4) * 16);
    uint32_t b_off[4];
#pragma unroll
    for (int nf2 = 0; nf2 < 4; nf2++)
        b_off[nf2] = (uint32_t)((lane & 15) * (LDB2 * 2)
                   + (warpN * 64 + nf2 * 16 + (lane >> 4) * 8) * 2);

#define ISSUE(st, kc) do { \
        cp16(uA[st][apart] + adst, asrc + (kc), asz); \
        _Pragma("unroll") \
        for (int q = 0; q < 4; q++) \
            cp16(uB[st][bpart[q]] + bdst[q], bsrc[q] + (size_t)(kc) * 256, 16); \
        CP_COMMIT(); \
    } while (0)

    ISSUE(0, 0);

#pragma unroll
    for (int c = 0; c < 8; c++) {
        if (c < 7) {
            ISSUE((c + 1) & 1, (c + 1) * 16);
            CP_WAIT(1);
        } else {
            CP_WAIT(0);
        }
        __syncthreads();
        const int st = c & 1;

        uint32_t ah[2][4], al[2][4];
#pragma unroll
        for (int mf = 0; mf < 2; mf++) {
            LDMX4(ah[mf][0], ah[mf][1], ah[mf][2], ah[mf][3], uA[st][0] + a_off[mf]);
            LDMX4(al[mf][0], al[mf][1], al[mf][2], al[mf][3], uA[st][1] + a_off[mf]);
        }
#pragma unroll
        for (int nf2 = 0; nf2 < 4; nf2++) {
            uint32_t bh[4], bl[4];
            LDMX4T(bh[0], bh[1], bh[2], bh[3], uB[st][0] + b_off[nf2]);
            LDMX4T(bl[0], bl[1], bl[2], bl[3], uB[st][1] + b_off[nf2]);
#pragma unroll
            for (int half = 0; half < 2; half++) {
                int nf = nf2 * 2 + half;
#pragma unroll
                for (int mf = 0; mf < 2; mf++) {
                    MMA16816(acc[mf][nf], ah[mf], bh[half * 2], bh[half * 2 + 1]);
                    MMA16816(acc[mf][nf], ah[mf], bl[half * 2], bl[half * 2 + 1]);
                    MMA16816(acc[mf][nf], al[mf], bh[half * 2], bh[half * 2 + 1]);
                }
            }
        }
        __syncthreads();
    }
#undef ISSUE

    // ---- epilogue: direct register stores ----
#pragma unroll
    for (int mf = 0; mf < 2; mf++) {
        int gr0 = block_row + warpM * 32 + mf * 16 + (lane >> 2);
#pragma unroll
        for (int nf = 0; nf < 8; nf++) {
            int cg = warpN * 64 + nf * 8 + (lane & 3) * 2;
            float bias0 = 0.f, bias1 = 0.f;
            float* dst;
            int col;
            if (cg < 128) {
                dst = g_h; col = cg;
            } else {
                dst = out; col = cg - 128;
                bias0 = b_res[col];
                bias1 = b_res[col + 1];
            }
            if (gr0 < n) {
                float2 o = make_float2(acc[mf][nf][0] + bias0,
                                       acc[mf][nf][1] + bias1);
                *(float2*)&dst[(size_t)gr0 * F + col] = o;
            }
            if (gr0 + 8 < n) {
                float2 o = make_float2(acc[mf][nf][2] + bias0,
                                       acc[mf][nf][3] + bias1);
                *(float2*)&dst[(size_t)(gr0 + 8) * F + col] = o;
            }
        }
    }
}

// ---------------- aggregate (gather) + self-loop + bias + ReLU + BN stats --
__global__ void aggregate_kernel(const float* __restrict__ b, int n) {
    __shared__ float bsum[F];
    __shared__ float bsq[F];
    const int t = threadIdx.x;
    if (t < F) { bsum[t] = 0.f; bsq[t] = 0.f; }
    __syncthreads();

    const int node = (blockIdx.x * blockDim.x + t) >> 5;
    const int lane = t & 31;

    if (node < n) {
        const float4* h4 = (const float4*)g_h;
        float dc = g_dinv[node];
        float dc2 = dc * dc;
        int j = g_off[node];
        int end = j + g_deg[node];

        float4 acc = h4[(size_t)node * 32 + lane];
        float4 bv = ((const float4*)b)[lane];
        acc.x = fmaf(acc.x, dc2, bv.x);
        acc.y = fmaf(acc.y, dc2, bv.y);
        acc.z = fmaf(acc.z, dc2, bv.z);
        acc.w = fmaf(acc.w, dc2, bv.w);

        // 4-way unrolled independent load chains
        for (; j + 3 < end; j += 4) {
            int r0 = g_src[j], r1 = g_src[j + 1];
            int r2 = g_src[j + 2], r3 = g_src[j + 3];
            float n0 = dc * g_dinv[r0];
            float n1 = dc * g_dinv[r1];
            float n2 = dc * g_dinv[r2];
            float n3 = dc * g_dinv[r3];
            float4 v0 = h4[(size_t)r0 * 32 + lane];
            float4 v1 = h4[(size_t)r1 * 32 + lane];
            float4 v2 = h4[(size_t)r2 * 32 + lane];
            float4 v3 = h4[(size_t)r3 * 32 + lane];
            acc.x = fmaf(v0.x, n0, acc.x); acc.y = fmaf(v0.y, n0, acc.y);
            acc.z = fmaf(v0.z, n0, acc.z); acc.w = fmaf(v0.w, n0, acc.w);
            acc.x = fmaf(v1.x, n1, acc.x); acc.y = fmaf(v1.y, n1, acc.y);
            acc.z = fmaf(v1.z, n1, acc.z); acc.w = fmaf(v1.w, n1, acc.w);
            acc.x = fmaf(v2.x, n2, acc.x); acc.y = fmaf(v2.y, n2, acc.y);
            acc.z = fmaf(v2.z, n2, acc.z); acc.w = fmaf(v2.w, n2, acc.w);
            acc.x = fmaf(v3.x, n3, acc.x); acc.y = fmaf(v3.y, n3, acc.y);
            acc.z = fmaf(v3.z, n3, acc.z); acc.w = fmaf(v3.w, n3, acc.w);
        }
        for (; j < end; j++) {
            int r = g_src[j];
            float nrm = dc * g_dinv[r];
            float4 v = h4[(size_t)r * 32 + lane];
            acc.x = fmaf(v.x, nrm, acc.x);
            acc.y = fmaf(v.y, nrm, acc.y);
            acc.z = fmaf(v.z, nrm, acc.z);
            acc.w = fmaf(v.w, nrm, acc.w);
        }
        acc.x = fmaxf(acc.x, 0.f);
        acc.y = fmaxf(acc.y, 0.f);
        acc.z = fmaxf(acc.z, 0.f);
        acc.w = fmaxf(acc.w, 0.f);
        ((float4*)g_agg)[(size_t)node * 32 + lane] = acc;

        int f0 = lane * 4;
        atomicAdd(&bsum[f0 + 0], acc.x);
        atomicAdd(&bsum[f0 + 1], acc.y);
        atomicAdd(&bsum[f0 + 2], acc.z);
        atomicAdd(&bsum[f0 + 3], acc.w);
        atomicAdd(&bsq[f0 + 0], acc.x * acc.x);
        atomicAdd(&bsq[f0 + 1], acc.y * acc.y);
        atomicAdd(&bsq[f0 + 2], acc.z * acc.z);
        atomicAdd(&bsq[f0 + 3], acc.w * acc.w);
    }
    __syncthreads();
    if (t < F) {
        atomicAdd(&g_sum[t], bsum[t]);
        atomicAdd(&g_sumsq[t], bsq[t]);
    }
}

// ---------------- fold mean/var/gamma/beta into scale/shift ----------------
__global__ void finalize_stats_kernel(const float* __restrict__ gamma,
                                      const float* __restrict__ beta, int n) {
    int f = threadIdx.x;
    if (f < F) {
        float inv_n = 1.f / (float)n;
        float mean = g_sum[f] * inv_n;
        float var = g_sumsq[f] * inv_n - mean * mean;
        float istd = rsqrtf(var + BN_EPS);
        float sc = gamma[f] * istd;
        g_scale[f] = sc;
        g_shift[f] = beta[f] - mean * sc;
    }
}

// ---------------- final: out += r*scale + shift (out holds res+b_res) -----
__global__ void final_kernel(float* __restrict__ out, int n) {
    int tid = blockIdx.x * blockDim.x + threadIdx.x;
    if (tid >= n * (F / 4)) return;
    int s = tid & 31;
    float4 a = ((const float4*)g_agg)[tid];
    float4 sc = ((const float4*)g_scale)[s];
    float4 sh = ((const float4*)g_shift)[s];
    float4 o = ((float4*)out)[tid];
    o.x += a.x * sc.x + sh.x;
    o.y += a.y * sc.y + sh.y;
    o.z += a.z * sc.z + sh.z;
    o.w += a.w * sc.w + sh.w;
    ((float4*)out)[tid] = o;
}

// ---------------- launch ----------------------------------------------------
static cudaStream_t s_csr = nullptr;
static cudaEvent_t s_evF = nullptr, s_evJ = nullptr;

extern "C" void kernel_launch(void* const* d_in, const int* in_sizes, int n_in,
                              void* d_out, int out_size) {
    const float* x        = (const float*)d_in[0];
    const void*  ei       = d_in[1];
    const float* W        = (const float*)d_in[2];
    const float* b        = (const float*)d_in[3];
    const float* gamma    = (const float*)d_in[4];
    const float* beta     = (const float*)d_in[5];
    const float* W_res    = (const float*)d_in[6];
    const float* b_res    = (const float*)d_in[7];
    float* out            = (float*)d_out;

    const int n = in_sizes[0] / F;
    const int E = in_sizes[1] / 2;
    const int nb = (n + SCAN_BLK - 1) / SCAN_BLK;

    if (s_csr == nullptr) {   // first (non-captured) call only; reused thereafter
        cudaStreamCreateWithFlags(&s_csr, cudaStreamNonBlocking);
        cudaEventCreateWithFlags(&s_evF, cudaEventDisableTiming);
        cudaEventCreateWithFlags(&s_evJ, cudaEventDisableTiming);
    }

    const int T = 256;
    detect_kernel<<<1, 32>>>(ei, n);                            // 1
    init_kernel<<<(n + T - 1) / T, T>>>(n);                     // 2

    // fork CSR branch NOW (only needs detect+init), before conv/gemm
    cudaEventRecord(s_evF, 0);
    cudaStreamWaitEvent(s_csr, s_evF, 0);
    deg_kernel<<<(E + T - 1) / T, T, 0, s_csr>>>(ei, E);
    scan1_kernel<<<nb, 1024, 0, s_csr>>>(n);
    scan2_kernel<<<1, 32, 0, s_csr>>>(nb);
    scan3_kernel<<<(n + T - 1) / T, T, 0, s_csr>>>(n);
    fill_kernel<<<(E + T - 1) / T, T, 0, s_csr>>>(ei, E);
    cudaEventRecord(s_evJ, s_csr);

    conv_kernel<<<32 + (n * 32 + T - 1) / T, T>>>(x, W, W_res, n);  // 3
    gemm_mma_kernel<<<(n + GM - 1) / GM, 256>>>(b_res, out, n);     // 4 (profiled)

    cudaStreamWaitEvent(0, s_evJ, 0);   // join before aggregate

    {
        long long work = (long long)n * 32;
        aggregate_kernel<<<(int)((work + T - 1) / T), T>>>(b, n);
    }
    finalize_stats_kernel<<<1, F>>>(gamma, beta, n);
    {
        int work = n * (F / 4);
        final_kernel<<<(work + T - 1) / T, T>>>(out, n);
    }
}

// round 11
// speedup vs baseline: 1.1016x; 1.0067x over previous
#include <cuda_runtime.h>
#include <cuda_bf16.h>
#include <stdint.h>

// Problem constants (fixed by the reference)
#define MAXN 100000
#define MAXE 600000
#define F 128
#define BN_EPS 1e-5f

#define SCAN_BLK 4096
#define NBMAX 32

// ---------------- device scratch (no allocations allowed) ----------------
__device__ __align__(16) float g_h[(size_t)MAXN * F];     // h = x @ W
__device__ __align__(16) float g_agg[(size_t)MAXN * F];   // relu(agg)
__device__ __align__(16) __nv_bfloat16 g_xh[(size_t)MAXN * F];
__device__ __align__(16) __nv_bfloat16 g_xl[(size_t)MAXN * F];
__device__ __align__(16) __nv_bfloat16 g_wh[128 * 256];   // [k][c]: c<128 W, c>=128 W_res
__device__ __align__(16) __nv_bfloat16 g_wl[128 * 256];
__device__ int   g_deg[MAXN + 4];
__device__ int   g_off[MAXN + 4];
__device__ int   g_cur[MAXN];
__device__ int   g_src[MAXE];
__device__ float g_dinv[MAXN];
__device__ int   g_bsum[NBMAX];
__device__ float g_sum[F];
__device__ float g_sumsq[F];
__device__ int   g_is64;

// ---------------- helpers ----------------
__device__ __forceinline__ uint32_t smem_u32(const void* p) {
    uint32_t a;
    asm("{ .reg .u64 t; cvta.to.shared.u64 t, %1; cvt.u32.u64 %0, t; }"
        : "=r"(a) : "l"(p));
    return a;
}
__device__ __forceinline__ void split_bf16(float v, __nv_bfloat16& h, __nv_bfloat16& l) {
    h = __float2bfloat16(v);
    l = __float2bfloat16(v - __bfloat162float(h));
}
__device__ __forceinline__ uint32_t pack_bf162(__nv_bfloat16 a, __nv_bfloat16 b) {
    __nv_bfloat162 p = __halves2bfloat162(a, b);
    return *reinterpret_cast<uint32_t*>(&p);
}
__device__ __forceinline__ void cp16(uint32_t dst, const void* src, int srcsize) {
    asm volatile("cp.async.ca.shared.global [%0], [%1], 16, %2;"
        :: "r"(dst), "l"(src), "r"(srcsize) : "memory");
}
#define CP_COMMIT() asm volatile("cp.async.commit_group;" ::: "memory")
#define CP_WAIT(N)  asm volatile("cp.async.wait_group %0;" :: "n"(N) : "memory")

#define LDMX4(r0, r1, r2, r3, addr) \
    asm volatile("ldmatrix.sync.aligned.m8n8.x4.shared.b16 {%0,%1,%2,%3}, [%4];" \
        : "=r"(r0), "=r"(r1), "=r"(r2), "=r"(r3) : "r"(addr))
#define LDMX4T(r0, r1, r2, r3, addr) \
    asm volatile("ldmatrix.sync.aligned.m8n8.x4.trans.shared.b16 {%0,%1,%2,%3}, [%4];" \
        : "=r"(r0), "=r"(r1), "=r"(r2), "=r"(r3) : "r"(addr))
#define MMA16816(c, a, b0, b1) \
    asm volatile("mma.sync.aligned.m16n8k16.row.col.f32.bf16.bf16.f32 " \
        "{%0,%1,%2,%3}, {%4,%5,%6,%7}, {%8,%9}, {%0,%1,%2,%3};" \
        : "+f"((c)[0]), "+f"((c)[1]), "+f"((c)[2]), "+f"((c)[3]) \
        : "r"((a)[0]), "r"((a)[1]), "r"((a)[2]), "r"((a)[3]), "r"(b0), "r"(b1))

// ---------------- init (+ inline edge dtype detect) ----------------
__global__ void init_kernel(const void* ei, int n) {
    int i = blockIdx.x * blockDim.x + threadIdx.x;
    if (i < n) g_deg[i] = 0;
    if (i < F) { g_sum[i] = 0.f; g_sumsq[i] = 0.f; }
    if (i == 0) {
        const long long* p = (const long long*)ei;
        int ok = 1;
#pragma unroll
        for (int q = 0; q < 16; q++) {
            long long v = p[q];
            if (v < 0 || v >= n) { ok = 0; break; }
        }
        g_is64 = ok;
    }
}

// ---------------- hi/lo bf16 conversion: W+W_res (blocks 0..31), x (rest) --
__global__ void conv_kernel(const float* __restrict__ X,
                            const float* __restrict__ Wm,
                            const float* __restrict__ Wres, int n) {
    const int tid = threadIdx.x;
    const int bid = blockIdx.x;
    if (bid < 32) {
        int idx = bid * 256 + tid;        // 0..8191
        int is_res = idx >> 12;
        int r = idx & 4095;
        int k = r >> 5, c4 = r & 31;
        const float* src = is_res ? Wres : Wm;
        float4 v = *(const float4*)&src[k * 128 + c4 * 4];
        __nv_bfloat16 h0, l0, h1, l1, h2, l2, h3, l3;
        split_bf16(v.x, h0, l0); split_bf16(v.y, h1, l1);
        split_bf16(v.z, h2, l2); split_bf16(v.w, h3, l3);
        int dst = k * 256 + is_res * 128 + c4 * 4;
        *(uint2*)&g_wh[dst] = make_uint2(pack_bf162(h0, h1), pack_bf162(h2, h3));
        *(uint2*)&g_wl[dst] = make_uint2(pack_bf162(l0, l1), pack_bf162(l2, l3));
    } else {
        int idx = (bid - 32) * 256 + tid;
        if (idx < n * 32) {
            float4 v = ((const float4*)X)[idx];
            __nv_bfloat16 h0, l0, h1, l1, h2, l2, h3, l3;
            split_bf16(v.x, h0, l0); split_bf16(v.y, h1, l1);
            split_bf16(v.z, h2, l2); split_bf16(v.w, h3, l3);
            *(uint2*)&g_xh[(size_t)idx * 4] =
                make_uint2(pack_bf162(h0, h1), pack_bf162(h2, h3));
            *(uint2*)&g_xl[(size_t)idx * 4] =
                make_uint2(pack_bf162(l0, l1), pack_bf162(l2, l3));
        }
    }
}

// ---------------- degree histogram over destination (col) ----------------
__global__ void deg_kernel(const void* __restrict__ ei, int E) {
    int e = blockIdx.x * blockDim.x + threadIdx.x;
    if (e < E) {
        int c;
        if (g_is64) c = (int)((const long long*)ei)[E + e];
        else        c = ((const int*)ei)[E + e];
        atomicAdd(&g_deg[c], 1);
    }
}

// ---------------- 3-phase scan ----------------
__global__ void scan1_kernel(int n) {
    __shared__ int wsum[32];
    const int t = threadIdx.x;
    const int lane = t & 31;
    const int w = t >> 5;
    const int idx = blockIdx.x * SCAN_BLK + t * 4;

    int d0 = 0, d1 = 0, d2 = 0, d3 = 0;
    if (idx + 3 < n) {
        int4 dd = *(const int4*)&g_deg[idx];
        d0 = dd.x; d1 = dd.y; d2 = dd.z; d3 = dd.w;
    } else {
        if (idx + 0 < n) d0 = g_deg[idx + 0];
        if (idx + 1 < n) d1 = g_deg[idx + 1];
        if (idx + 2 < n) d2 = g_deg[idx + 2];
        if (idx + 3 < n) d3 = g_deg[idx + 3];
    }
    int s = d0 + d1 + d2 + d3;
    int v = s;
#pragma unroll
    for (int o = 1; o < 32; o <<= 1) {
        int a = __shfl_up_sync(0xffffffffu, v, o);
        if (lane >= o) v += a;
    }
    if (lane == 31) wsum[w] = v;
    __syncthreads();
    if (w == 0) {
        int sv = wsum[lane];
#pragma unroll
        for (int o = 1; o < 32; o <<= 1) {
            int a = __shfl_up_sync(0xffffffffu, sv, o);
            if (lane >= o) sv += a;
        }
        wsum[lane] = sv;
    }
    __syncthreads();
    int excl = (w ? wsum[w - 1] : 0) + v - s;

    if (idx + 3 < n) {
        int4 oo = make_int4(excl, excl + d0, excl + d0 + d1, excl + d0 + d1 + d2);
        *(int4*)&g_off[idx] = oo;
        g_dinv[idx + 0] = rsqrtf((float)(d0 + 1));
        g_dinv[idx + 1] = rsqrtf((float)(d1 + 1));
        g_dinv[idx + 2] = rsqrtf((float)(d2 + 1));
        g_dinv[idx + 3] = rsqrtf((float)(d3 + 1));
    } else {
        int e = excl;
        if (idx + 0 < n) { g_off[idx + 0] = e; g_dinv[idx + 0] = rsqrtf((float)(d0 + 1)); e += d0; }
        if (idx + 1 < n) { g_off[idx + 1] = e; g_dinv[idx + 1] = rsqrtf((float)(d1 + 1)); e += d1; }
        if (idx + 2 < n) { g_off[idx + 2] = e; g_dinv[idx + 2] = rsqrtf((float)(d2 + 1)); e += d2; }
        if (idx + 3 < n) { g_off[idx + 3] = e; g_dinv[idx + 3] = rsqrtf((float)(d3 + 1)); }
    }
    if (t == 0) g_bsum[blockIdx.x] = wsum[31];
}

__global__ void scan2_kernel(int nb) {
    int lane = threadIdx.x;
    int v = (lane < nb) ? g_bsum[lane] : 0;
    int orig = v;
#pragma unroll
    for (int o = 1; o < 32; o <<= 1) {
        int a = __shfl_up_sync(0xffffffffu, v, o);
        if (lane >= o) v += a;
    }
    if (lane < nb) g_bsum[lane] = v - orig;
}

__global__ void scan3_kernel(int n) {
    int i = blockIdx.x * blockDim.x + threadIdx.x;
    if (i < n) {
        int o = g_off[i] + g_bsum[i >> 12];
        g_off[i] = o;
        g_cur[i] = o;
    }
}

// ---------------- CSR fill ----------------
__global__ void fill_kernel(const void* __restrict__ ei, int E) {
    int e = blockIdx.x * blockDim.x + threadIdx.x;
    if (e < E) {
        int r, c;
        if (g_is64) {
            r = (int)((const long long*)ei)[e];
            c = (int)((const long long*)ei)[E + e];
        } else {
            r = ((const int*)ei)[e];
            c = ((const int*)ei)[E + e];
        }
        int p = atomicAdd(&g_cur[c], 1);
        g_src[p] = r;
    }
}

// ---------------- mma.sync bf16 GEMM, 3-stage cp.async, low-reg -----------
// Block: 256 threads (2x4 warps), tile 64 rows x 128 cols.
// grid.x = 2*ceil(n/64): even blocks -> W half -> g_h; odd -> W_res -> out.
// Warp tile 32x32 (acc 32 regs). 3-term hi/lo product (rel err ~5e-6).
#define GM 64
#define LDA2 24      // A smem stride (bf16)
#define LDB3 136     // B smem stride (bf16): 272 B

__global__ void __launch_bounds__(256, 2)
gemm_mma_kernel(const float* __restrict__ b_res, float* __restrict__ out, int n) {
    __shared__ __align__(16) __nv_bfloat16 sA[3][2][GM * LDA2];   // 18 KB
    __shared__ __align__(16) __nv_bfloat16 sB[3][2][16 * LDB3];   // 25.5 KB

    const int tid = threadIdx.x;
    const int lane = tid & 31;
    const int wid = tid >> 5;
    const int warpM = wid >> 2;          // 0..1
    const int warpN = wid & 3;           // 0..3
    const int rb = blockIdx.x >> 1;
    const int half = blockIdx.x & 1;     // 0: W -> g_h, 1: W_res -> out
    const int block_row = rb * GM;

    float acc[2][4][4];
#pragma unroll
    for (int i = 0; i < 2; i++)
#pragma unroll
        for (int j = 0; j < 4; j++)
#pragma unroll
            for (int q = 0; q < 4; q++) acc[i][j][q] = 0.f;

    uint32_t uA[3][2], uB[3][2];
#pragma unroll
    for (int s = 0; s < 3; s++) {
#pragma unroll
        for (int p = 0; p < 2; p++) {
            uA[s][p] = smem_u32(sA[s][p]);
            uB[s][p] = smem_u32(sB[s][p]);
        }
    }

    // ---- cp.async roles ----
    // A: 256 segs (2 parts x 64 rows x 2 segs), 1 per thread
    const int apart = tid >> 7;
    const int arow = (tid & 127) >> 1;
    const int aseg = tid & 1;
    const int agr = block_row + arow;
    const __nv_bfloat16* asrc =
        (apart ? g_xl : g_xh) + (size_t)(agr < n ? agr : 0) * F + aseg * 8;
    const int asz = (agr < n) ? 16 : 0;
    const uint32_t adst = (uint32_t)(arow * LDA2 + aseg * 8) * 2;

    // B: per part 256 segs (16 k x 16 segs); thread handles part q, 1 seg each
    const int bkr = tid >> 4;            // 0..15
    const int bsg = tid & 15;            // 0..15
    const __nv_bfloat16* bsrc[2];
    bsrc[0] = g_wh + bkr * 256 + half * 128 + bsg * 8;
    bsrc[1] = g_wl + bkr * 256 + half * 128 + bsg * 8;
    const uint32_t bdst = (uint32_t)(bkr * LDB3 + bsg * 8) * 2;

    // ldmatrix offsets
    uint32_t a_off[2];
#pragma unroll
    for (int mf = 0; mf < 2; mf++)
        a_off[mf] = (uint32_t)((warpM * 32 + mf * 16 + (lane & 15)) * (LDA2 * 2)
                  + (lane >> 4) * 16);
    uint32_t b_off[2];
#pragma unroll
    for (int nf2 = 0; nf2 < 2; nf2++)
        b_off[nf2] = (uint32_t)((lane & 15) * (LDB3 * 2)
                   + (warpN * 32 + nf2 * 16 + (lane >> 4) * 8) * 2);

#define ISSUE(st, kc) do { \
        cp16(uA[st][apart] + adst, asrc + (kc), asz); \
        cp16(uB[st][0] + bdst, bsrc[0] + (size_t)(kc) * 256, 16); \
        cp16(uB[st][1] + bdst, bsrc[1] + (size_t)(kc) * 256, 16); \
        CP_COMMIT(); \
    } while (0)

    ISSUE(0, 0);
    ISSUE(1, 16);

#pragma unroll
    for (int c = 0; c < 8; c++) {
        if (c < 6) {
            ISSUE((c + 2) % 3, (c + 2) * 16);
            CP_WAIT(2);
        } else if (c == 6) {
            CP_WAIT(1);
        } else {
            CP_WAIT(0);
        }
        __syncthreads();
        const int st = c % 3;

        uint32_t ah[2][4], al[2][4];
#pragma unroll
        for (int mf = 0; mf < 2; mf++) {
            LDMX4(ah[mf][0], ah[mf][1], ah[mf][2], ah[mf][3], uA[st][0] + a_off[mf]);
            LDMX4(al[mf][0], al[mf][1], al[mf][2], al[mf][3], uA[st][1] + a_off[mf]);
        }
#pragma unroll
        for (int nf2 = 0; nf2 < 2; nf2++) {
            uint32_t bh[4], bl[4];
            LDMX4T(bh[0], bh[1], bh[2], bh[3], uB[st][0] + b_off[nf2]);
            LDMX4T(bl[0], bl[1], bl[2], bl[3], uB[st][1] + b_off[nf2]);
#pragma unroll
            for (int h2 = 0; h2 < 2; h2++) {
                int nf = nf2 * 2 + h2;
#pragma unroll
                for (int mf = 0; mf < 2; mf++) {
                    MMA16816(acc[mf][nf], ah[mf], bh[h2 * 2], bh[h2 * 2 + 1]);
                    MMA16816(acc[mf][nf], ah[mf], bl[h2 * 2], bl[h2 * 2 + 1]);
                    MMA16816(acc[mf][nf], al[mf], bh[h2 * 2], bh[h2 * 2 + 1]);
                }
            }
        }
        __syncthreads();
    }
#undef ISSUE

    // ---- epilogue ----
    float* dst = half ? out : g_h;
#pragma unroll
    for (int mf = 0; mf < 2; mf++) {
        int gr0 = block_row + warpM * 32 + mf * 16 + (lane >> 2);
#pragma unroll
        for (int nf = 0; nf < 4; nf++) {
            int col = warpN * 32 + nf * 8 + (lane & 3) * 2;
            float bias0 = 0.f, bias1 = 0.f;
            if (half) { bias0 = b_res[col]; bias1 = b_res[col + 1]; }
            if (gr0 < n) {
                float2 o = make_float2(acc[mf][nf][0] + bias0,
                                       acc[mf][nf][1] + bias1);
                *(float2*)&dst[(size_t)gr0 * F + col] = o;
            }
            if (gr0 + 8 < n) {
                float2 o = make_float2(acc[mf][nf][2] + bias0,
                                       acc[mf][nf][3] + bias1);
                *(float2*)&dst[(size_t)(gr0 + 8) * F + col] = o;
            }
        }
    }
}

// ---------------- aggregate (gather) + self-loop + bias + ReLU + BN stats --
__global__ void aggregate_kernel(const float* __restrict__ b, int n) {
    __shared__ float bsum[F];
    __shared__ float bsq[F];
    const int t = threadIdx.x;
    if (t < F) { bsum[t] = 0.f; bsq[t] = 0.f; }
    __syncthreads();

    const int node = (blockIdx.x * blockDim.x + t) >> 5;
    const int lane = t & 31;

    if (node < n) {
        const float4* h4 = (const float4*)g_h;
        float dc = g_dinv[node];
        float dc2 = dc * dc;
        int j = g_off[node];
        int end = j + g_deg[node];

        float4 acc = h4[(size_t)node * 32 + lane];
        float4 bv = ((const float4*)b)[lane];
        acc.x = fmaf(acc.x, dc2, bv.x);
        acc.y = fmaf(acc.y, dc2, bv.y);
        acc.z = fmaf(acc.z, dc2, bv.z);
        acc.w = fmaf(acc.w, dc2, bv.w);

        for (; j + 3 < end; j += 4) {
            int r0 = g_src[j], r1 = g_src[j + 1];
            int r2 = g_src[j + 2], r3 = g_src[j + 3];
            float n0 = dc * g_dinv[r0];
            float n1 = dc * g_dinv[r1];
            float n2 = dc * g_dinv[r2];
            float n3 = dc * g_dinv[r3];
            float4 v0 = h4[(size_t)r0 * 32 + lane];
            float4 v1 = h4[(size_t)r1 * 32 + lane];
            float4 v2 = h4[(size_t)r2 * 32 + lane];
            float4 v3 = h4[(size_t)r3 * 32 + lane];
            acc.x = fmaf(v0.x, n0, acc.x); acc.y = fmaf(v0.y, n0, acc.y);
            acc.z = fmaf(v0.z, n0, acc.z); acc.w = fmaf(v0.w, n0, acc.w);
            acc.x = fmaf(v1.x, n1, acc.x); acc.y = fmaf(v1.y, n1, acc.y);
            acc.z = fmaf(v1.z, n1, acc.z); acc.w = fmaf(v1.w, n1, acc.w);
            acc.x = fmaf(v2.x, n2, acc.x); acc.y = fmaf(v2.y, n2, acc.y);
            acc.z = fmaf(v2.z, n2, acc.z); acc.w = fmaf(v2.w, n2, acc.w);
            acc.x = fmaf(v3.x, n3, acc.x); acc.y = fmaf(v3.y, n3, acc.y);
            acc.z = fmaf(v3.z, n3, acc.z); acc.w = fmaf(v3.w, n3, acc.w);
        }
        for (; j < end; j++) {
            int r = g_src[j];
            float nrm = dc * g_dinv[r];
            float4 v = h4[(size_t)r * 32 + lane];
            acc.x = fmaf(v.x, nrm, acc.x);
            acc.y = fmaf(v.y, nrm, acc.y);
            acc.z = fmaf(v.z, nrm, acc.z);
            acc.w = fmaf(v.w, nrm, acc.w);
        }
        acc.x = fmaxf(acc.x, 0.f);
        acc.y = fmaxf(acc.y, 0.f);
        acc.z = fmaxf(acc.z, 0.f);
        acc.w = fmaxf(acc.w, 0.f);
        ((float4*)g_agg)[(size_t)node * 32 + lane] = acc;

        int f0 = lane * 4;
        atomicAdd(&bsum[f0 + 0], acc.x);
        atomicAdd(&bsum[f0 + 1], acc.y);
        atomicAdd(&bsum[f0 + 2], acc.z);
        atomicAdd(&bsum[f0 + 3], acc.w);
        atomicAdd(&bsq[f0 + 0], acc.x * acc.x);
        atomicAdd(&bsq[f0 + 1], acc.y * acc.y);
        atomicAdd(&bsq[f0 + 2], acc.z * acc.z);
        atomicAdd(&bsq[f0 + 3], acc.w * acc.w);
    }
    __syncthreads();
    if (t < F) {
        atomicAdd(&g_sum[t], bsum[t]);
        atomicAdd(&g_sumsq[t], bsq[t]);
    }
}

// ---------------- final: out += relu(agg)*scale + shift (fused BN fold) ----
__global__ void final_kernel(float* __restrict__ out,
                             const float* __restrict__ gamma,
                             const float* __restrict__ beta, int n) {
    __shared__ float ssc[F];
    __shared__ float ssh[F];
    const int t = threadIdx.x;
    if (t < F) {
        float inv_n = 1.f / (float)n;
        float mean = g_sum[t] * inv_n;
        float var = g_sumsq[t] * inv_n - mean * mean;
        float istd = rsqrtf(var + BN_EPS);
        float sc = gamma[t] * istd;
        ssc[t] = sc;
        ssh[t] = beta[t] - mean * sc;
    }
    __syncthreads();

    int tid = blockIdx.x * blockDim.x + t;
    if (tid >= n * (F / 4)) return;
    int s = tid & 31;
    float4 a = ((const float4*)g_agg)[tid];
    float4 sc = *(const float4*)&ssc[s * 4];
    float4 sh = *(const float4*)&ssh[s * 4];
    float4 o = ((float4*)out)[tid];
    o.x += a.x * sc.x + sh.x;
    o.y += a.y * sc.y + sh.y;
    o.z += a.z * sc.z + sh.z;
    o.w += a.w * sc.w + sh.w;
    ((float4*)out)[tid] = o;
}

// ---------------- launch ----------------------------------------------------
static cudaStream_t s_csr = nullptr;
static cudaEvent_t s_evF = nullptr, s_evJ = nullptr;

extern "C" void kernel_launch(void* const* d_in, const int* in_sizes, int n_in,
                              void* d_out, int out_size) {
    const float* x        = (const float*)d_in[0];
    const void*  ei       = d_in[1];
    const float* W        = (const float*)d_in[2];
    const float* b        = (const float*)d_in[3];
    const float* gamma    = (const float*)d_in[4];
    const float* beta     = (const float*)d_in[5];
    const float* W_res    = (const float*)d_in[6];
    const float* b_res    = (const float*)d_in[7];
    float* out            = (float*)d_out;

    const int n = in_sizes[0] / F;
    const int E = in_sizes[1] / 2;
    const int nb = (n + SCAN_BLK - 1) / SCAN_BLK;

    if (s_csr == nullptr) {   // first (non-captured) call only; reused thereafter
        cudaStreamCreateWithFlags(&s_csr, cudaStreamNonBlocking);
        cudaEventCreateWithFlags(&s_evF, cudaEventDisableTiming);
        cudaEventCreateWithFlags(&s_evJ, cudaEventDisableTiming);
    }

    const int T = 256;
    init_kernel<<<(n + T - 1) / T, T>>>(ei, n);                 // 1 (detect fused)

    // fork CSR branch (needs only init), overlaps conv+gemm
    cudaEventRecord(s_evF, 0);
    cudaStreamWaitEvent(s_csr, s_evF, 0);
    deg_kernel<<<(E + T - 1) / T, T, 0, s_csr>>>(ei, E);
    scan1_kernel<<<nb, 1024, 0, s_csr>>>(n);
    scan2_kernel<<<1, 32, 0, s_csr>>>(nb);
    scan3_kernel<<<(n + T - 1) / T, T, 0, s_csr>>>(n);
    fill_kernel<<<(E + T - 1) / T, T, 0, s_csr>>>(ei, E);
    cudaEventRecord(s_evJ, s_csr);

    conv_kernel<<<32 + (n * 32 + T - 1) / T, T>>>(x, W, W_res, n);
    gemm_mma_kernel<<<2 * ((n + GM - 1) / GM), 256>>>(b_res, out, n);

    cudaStreamWaitEvent(0, s_evJ, 0);   // join before aggregate

    {
        long long work = (long long)n * 32;
        aggregate_kernel<<<(int)((work + T - 1) / T), T>>>(b, n);
    }
    {
        int work = n * (F / 4);
        final_kernel<<<(work + T - 1) / T, T>>>(out, gamma, beta, n);
    }
}

// round 12
// speedup vs baseline: 1.1107x; 1.0083x over previous
#include <cuda_runtime.h>
#include <cuda_bf16.h>
#include <stdint.h>

// Problem constants (fixed by the reference)
#define MAXN 100000
#define MAXE 600000
#define F 128
#define BN_EPS 1e-5f

#define SCAN_BLK 4096
#define NBMAX 32

// ---------------- device scratch (no allocations allowed) ----------------
__device__ __align__(16) float g_h[(size_t)MAXN * F];     // h = x @ W
__device__ __align__(16) float g_agg[(size_t)MAXN * F];   // relu(agg)
__device__ __align__(16) __nv_bfloat16 g_xh[(size_t)MAXN * F];
__device__ __align__(16) __nv_bfloat16 g_xl[(size_t)MAXN * F];
__device__ __align__(16) __nv_bfloat16 g_wh[128 * 256];   // [k][c]: c<128 W, c>=128 W_res
__device__ __align__(16) __nv_bfloat16 g_wl[128 * 256];
__device__ int   g_deg[MAXN + 4];
__device__ int   g_off[MAXN + 4];
__device__ int   g_cur[MAXN];
__device__ int   g_src[MAXE];
__device__ float g_dinv[MAXN];
__device__ int   g_bsum[NBMAX];
__device__ float g_sum[F];
__device__ float g_sumsq[F];
__device__ int   g_is64;

// ---------------- helpers ----------------
__device__ __forceinline__ uint32_t smem_u32(const void* p) {
    uint32_t a;
    asm("{ .reg .u64 t; cvta.to.shared.u64 t, %1; cvt.u32.u64 %0, t; }"
        : "=r"(a) : "l"(p));
    return a;
}
__device__ __forceinline__ void split_bf16(float v, __nv_bfloat16& h, __nv_bfloat16& l) {
    h = __float2bfloat16(v);
    l = __float2bfloat16(v - __bfloat162float(h));
}
__device__ __forceinline__ uint32_t pack_bf162(__nv_bfloat16 a, __nv_bfloat16 b) {
    __nv_bfloat162 p = __halves2bfloat162(a, b);
    return *reinterpret_cast<uint32_t*>(&p);
}
__device__ __forceinline__ void cp16(uint32_t dst, const void* src, int srcsize) {
    asm volatile("cp.async.ca.shared.global [%0], [%1], 16, %2;"
        :: "r"(dst), "l"(src), "r"(srcsize) : "memory");
}
#define CP_COMMIT() asm volatile("cp.async.commit_group;" ::: "memory")
#define CP_WAIT(N)  asm volatile("cp.async.wait_group %0;" :: "n"(N) : "memory")

#define LDMX4(r0, r1, r2, r3, addr) \
    asm volatile("ldmatrix.sync.aligned.m8n8.x4.shared.b16 {%0,%1,%2,%3}, [%4];" \
        : "=r"(r0), "=r"(r1), "=r"(r2), "=r"(r3) : "r"(addr))
#define LDMX4T(r0, r1, r2, r3, addr) \
    asm volatile("ldmatrix.sync.aligned.m8n8.x4.trans.shared.b16 {%0,%1,%2,%3}, [%4];" \
        : "=r"(r0), "=r"(r1), "=r"(r2), "=r"(r3) : "r"(addr))
#define MMA16816(c, a, b0, b1) \
    asm volatile("mma.sync.aligned.m16n8k16.row.col.f32.bf16.bf16.f32 " \
        "{%0,%1,%2,%3}, {%4,%5,%6,%7}, {%8,%9}, {%0,%1,%2,%3};" \
        : "+f"((c)[0]), "+f"((c)[1]), "+f"((c)[2]), "+f"((c)[3]) \
        : "r"((a)[0]), "r"((a)[1]), "r"((a)[2]), "r"((a)[3]), "r"(b0), "r"(b1))

// ---------------- init (+ inline edge dtype detect) ----------------
__global__ void init_kernel(const void* ei, int n) {
    int i = blockIdx.x * blockDim.x + threadIdx.x;
    if (i < n) g_deg[i] = 0;
    if (i < F) { g_sum[i] = 0.f; g_sumsq[i] = 0.f; }
    if (i == 0) {
        const long long* p = (const long long*)ei;
        int ok = 1;
#pragma unroll
        for (int q = 0; q < 16; q++) {
            long long v = p[q];
            if (v < 0 || v >= n) { ok = 0; break; }
        }
        g_is64 = ok;
    }
}

// ---------------- hi/lo bf16 conversion: W+W_res (blocks 0..31), x (rest) --
__global__ void conv_kernel(const float* __restrict__ X,
                            const float* __restrict__ Wm,
                            const float* __restrict__ Wres, int n) {
    const int tid = threadIdx.x;
    const int bid = blockIdx.x;
    if (bid < 32) {
        int idx = bid * 256 + tid;        // 0..8191
        int is_res = idx >> 12;
        int r = idx & 4095;
        int k = r >> 5, c4 = r & 31;
        const float* src = is_res ? Wres : Wm;
        float4 v = *(const float4*)&src[k * 128 + c4 * 4];
        __nv_bfloat16 h0, l0, h1, l1, h2, l2, h3, l3;
        split_bf16(v.x, h0, l0); split_bf16(v.y, h1, l1);
        split_bf16(v.z, h2, l2); split_bf16(v.w, h3, l3);
        int dst = k * 256 + is_res * 128 + c4 * 4;
        *(uint2*)&g_wh[dst] = make_uint2(pack_bf162(h0, h1), pack_bf162(h2, h3));
        *(uint2*)&g_wl[dst] = make_uint2(pack_bf162(l0, l1), pack_bf162(l2, l3));
    } else {
        int idx = (bid - 32) * 256 + tid;
        if (idx < n * 32) {
            float4 v = ((const float4*)X)[idx];
            __nv_bfloat16 h0, l0, h1, l1, h2, l2, h3, l3;
            split_bf16(v.x, h0, l0); split_bf16(v.y, h1, l1);
            split_bf16(v.z, h2, l2); split_bf16(v.w, h3, l3);
            *(uint2*)&g_xh[(size_t)idx * 4] =
                make_uint2(pack_bf162(h0, h1), pack_bf162(h2, h3));
            *(uint2*)&g_xl[(size_t)idx * 4] =
                make_uint2(pack_bf162(l0, l1), pack_bf162(l2, l3));
        }
    }
}

// ---------------- degree histogram over destination (col) ----------------
__global__ void deg_kernel(const void* __restrict__ ei, int E) {
    int e = blockIdx.x * blockDim.x + threadIdx.x;
    if (e < E) {
        int c;
        if (g_is64) c = (int)((const long long*)ei)[E + e];
        else        c = ((const int*)ei)[E + e];
        atomicAdd(&g_deg[c], 1);
    }
}

// ---------------- 3-phase scan ----------------
__global__ void scan1_kernel(int n) {
    __shared__ int wsum[32];
    const int t = threadIdx.x;
    const int lane = t & 31;
    const int w = t >> 5;
    const int idx = blockIdx.x * SCAN_BLK + t * 4;

    int d0 = 0, d1 = 0, d2 = 0, d3 = 0;
    if (idx + 3 < n) {
        int4 dd = *(const int4*)&g_deg[idx];
        d0 = dd.x; d1 = dd.y; d2 = dd.z; d3 = dd.w;
    } else {
        if (idx + 0 < n) d0 = g_deg[idx + 0];
        if (idx + 1 < n) d1 = g_deg[idx + 1];
        if (idx + 2 < n) d2 = g_deg[idx + 2];
        if (idx + 3 < n) d3 = g_deg[idx + 3];
    }
    int s = d0 + d1 + d2 + d3;
    int v = s;
#pragma unroll
    for (int o = 1; o < 32; o <<= 1) {
        int a = __shfl_up_sync(0xffffffffu, v, o);
        if (lane >= o) v += a;
    }
    if (lane == 31) wsum[w] = v;
    __syncthreads();
    if (w == 0) {
        int sv = wsum[lane];
#pragma unroll
        for (int o = 1; o < 32; o <<= 1) {
            int a = __shfl_up_sync(0xffffffffu, sv, o);
            if (lane >= o) sv += a;
        }
        wsum[lane] = sv;
    }
    __syncthreads();
    int excl = (w ? wsum[w - 1] : 0) + v - s;

    if (idx + 3 < n) {
        int4 oo = make_int4(excl, excl + d0, excl + d0 + d1, excl + d0 + d1 + d2);
        *(int4*)&g_off[idx] = oo;
        g_dinv[idx + 0] = rsqrtf((float)(d0 + 1));
        g_dinv[idx + 1] = rsqrtf((float)(d1 + 1));
        g_dinv[idx + 2] = rsqrtf((float)(d2 + 1));
        g_dinv[idx + 3] = rsqrtf((float)(d3 + 1));
    } else {
        int e = excl;
        if (idx + 0 < n) { g_off[idx + 0] = e; g_dinv[idx + 0] = rsqrtf((float)(d0 + 1)); e += d0; }
        if (idx + 1 < n) { g_off[idx + 1] = e; g_dinv[idx + 1] = rsqrtf((float)(d1 + 1)); e += d1; }
        if (idx + 2 < n) { g_off[idx + 2] = e; g_dinv[idx + 2] = rsqrtf((float)(d2 + 1)); e += d2; }
        if (idx + 3 < n) { g_off[idx + 3] = e; g_dinv[idx + 3] = rsqrtf((float)(d3 + 1)); }
    }
    if (t == 0) g_bsum[blockIdx.x] = wsum[31];
}

__global__ void scan2_kernel(int nb) {
    int lane = threadIdx.x;
    int v = (lane < nb) ? g_bsum[lane] : 0;
    int orig = v;
#pragma unroll
    for (int o = 1; o < 32; o <<= 1) {
        int a = __shfl_up_sync(0xffffffffu, v, o);
        if (lane >= o) v += a;
    }
    if (lane < nb) g_bsum[lane] = v - orig;
}

__global__ void scan3_kernel(int n) {
    int i = blockIdx.x * blockDim.x + threadIdx.x;
    if (i < n) {
        int o = g_off[i] + g_bsum[i >> 12];
        g_off[i] = o;
        g_cur[i] = o;
    }
}

// ---------------- CSR fill ----------------
__global__ void fill_kernel(const void* __restrict__ ei, int E) {
    int e = blockIdx.x * blockDim.x + threadIdx.x;
    if (e < E) {
        int r, c;
        if (g_is64) {
            r = (int)((const long long*)ei)[e];
            c = (int)((const long long*)ei)[E + e];
        } else {
            r = ((const int*)ei)[e];
            c = ((const int*)ei)[E + e];
        }
        int p = atomicAdd(&g_cur[c], 1);
        g_src[p] = r;
    }
}

// ---------------- mma.sync bf16 GEMM (one weight half per launch) ---------
// Block: 256 threads (2x4 warps), tile 64 rows x 128 cols.
// half=0: x@W -> g_h.  half=1: x@W_res + b_res -> out.
// Warp tile 32x32. 3-term hi/lo product (rel err ~5e-6). 3-stage cp.async.
#define GM 64
#define LDA2 24      // A smem stride (bf16)
#define LDB3 136     // B smem stride (bf16)

__global__ void __launch_bounds__(256, 2)
gemm_mma_kernel(const float* __restrict__ b_res, float* __restrict__ out,
                int n, int half) {
    __shared__ __align__(16) __nv_bfloat16 sA[3][2][GM * LDA2];   // 18 KB
    __shared__ __align__(16) __nv_bfloat16 sB[3][2][16 * LDB3];   // 25.5 KB

    const int tid = threadIdx.x;
    const int lane = tid & 31;
    const int wid = tid >> 5;
    const int warpM = wid >> 2;          // 0..1
    const int warpN = wid & 3;           // 0..3
    const int block_row = blockIdx.x * GM;

    float acc[2][4][4];
#pragma unroll
    for (int i = 0; i < 2; i++)
#pragma unroll
        for (int j = 0; j < 4; j++)
#pragma unroll
            for (int q = 0; q < 4; q++) acc[i][j][q] = 0.f;

    uint32_t uA[3][2], uB[3][2];
#pragma unroll
    for (int s = 0; s < 3; s++) {
#pragma unroll
        for (int p = 0; p < 2; p++) {
            uA[s][p] = smem_u32(sA[s][p]);
            uB[s][p] = smem_u32(sB[s][p]);
        }
    }

    // ---- cp.async roles ----
    const int apart = tid >> 7;
    const int arow = (tid & 127) >> 1;
    const int aseg = tid & 1;
    const int agr = block_row + arow;
    const __nv_bfloat16* asrc =
        (apart ? g_xl : g_xh) + (size_t)(agr < n ? agr : 0) * F + aseg * 8;
    const int asz = (agr < n) ? 16 : 0;
    const uint32_t adst = (uint32_t)(arow * LDA2 + aseg * 8) * 2;

    const int bkr = tid >> 4;            // 0..15
    const int bsg = tid & 15;            // 0..15
    const __nv_bfloat16* bsrc[2];
    bsrc[0] = g_wh + bkr * 256 + half * 128 + bsg * 8;
    bsrc[1] = g_wl + bkr * 256 + half * 128 + bsg * 8;
    const uint32_t bdst = (uint32_t)(bkr * LDB3 + bsg * 8) * 2;

    uint32_t a_off[2];
#pragma unroll
    for (int mf = 0; mf < 2; mf++)
        a_off[mf] = (uint32_t)((warpM * 32 + mf * 16 + (lane & 15)) * (LDA2 * 2)
                  + (lane >> 4) * 16);
    uint32_t b_off[2];
#pragma unroll
    for (int nf2 = 0; nf2 < 2; nf2++)
        b_off[nf2] = (uint32_t)((lane & 15) * (LDB3 * 2)
                   + (warpN * 32 + nf2 * 16 + (lane >> 4) * 8) * 2);

#define ISSUE(st, kc) do { \
        cp16(uA[st][apart] + adst, asrc + (kc), asz); \
        cp16(uB[st][0] + bdst, bsrc[0] + (size_t)(kc) * 256, 16); \
        cp16(uB[st][1] + bdst, bsrc[1] + (size_t)(kc) * 256, 16); \
        CP_COMMIT(); \
    } while (0)

    ISSUE(0, 0);
    ISSUE(1, 16);

#pragma unroll
    for (int c = 0; c < 8; c++) {
        if (c < 6) {
            ISSUE((c + 2) % 3, (c + 2) * 16);
            CP_WAIT(2);
        } else if (c == 6) {
            CP_WAIT(1);
        } else {
            CP_WAIT(0);
        }
        __syncthreads();
        const int st = c % 3;

        uint32_t ah[2][4], al[2][4];
#pragma unroll
        for (int mf = 0; mf < 2; mf++) {
            LDMX4(ah[mf][0], ah[mf][1], ah[mf][2], ah[mf][3], uA[st][0] + a_off[mf]);
            LDMX4(al[mf][0], al[mf][1], al[mf][2], al[mf][3], uA[st][1] + a_off[mf]);
        }
#pragma unroll
        for (int nf2 = 0; nf2 < 2; nf2++) {
            uint32_t bh[4], bl[4];
            LDMX4T(bh[0], bh[1], bh[2], bh[3], uB[st][0] + b_off[nf2]);
            LDMX4T(bl[0], bl[1], bl[2], bl[3], uB[st][1] + b_off[nf2]);
#pragma unroll
            for (int h2 = 0; h2 < 2; h2++) {
                int nf = nf2 * 2 + h2;
#pragma unroll
                for (int mf = 0; mf < 2; mf++) {
                    MMA16816(acc[mf][nf], ah[mf], bh[h2 * 2], bh[h2 * 2 + 1]);
                    MMA16816(acc[mf][nf], ah[mf], bl[h2 * 2], bl[h2 * 2 + 1]);
                    MMA16816(acc[mf][nf], al[mf], bh[h2 * 2], bh[h2 * 2 + 1]);
                }
            }
        }
        __syncthreads();
    }
#undef ISSUE

    // ---- epilogue ----
    float* dst = half ? out : g_h;
#pragma unroll
    for (int mf = 0; mf < 2; mf++) {
        int gr0 = block_row + warpM * 32 + mf * 16 + (lane >> 2);
#pragma unroll
        for (int nf = 0; nf < 4; nf++) {
            int col = warpN * 32 + nf * 8 + (lane & 3) * 2;
            float bias0 = 0.f, bias1 = 0.f;
            if (half) { bias0 = b_res[col]; bias1 = b_res[col + 1]; }
            if (gr0 < n) {
                float2 o = make_float2(acc[mf][nf][0] + bias0,
                                       acc[mf][nf][1] + bias1);
                *(float2*)&dst[(size_t)gr0 * F + col] = o;
            }
            if (gr0 + 8 < n) {
                float2 o = make_float2(acc[mf][nf][2] + bias0,
                                       acc[mf][nf][3] + bias1);
                *(float2*)&dst[(size_t)(gr0 + 8) * F + col] = o;
            }
        }
    }
}

// ---------------- aggregate (gather) + self-loop + bias + ReLU + BN stats --
__global__ void aggregate_kernel(const float* __restrict__ b, int n) {
    __shared__ float bsum[F];
    __shared__ float bsq[F];
    const int t = threadIdx.x;
    if (t < F) { bsum[t] = 0.f; bsq[t] = 0.f; }
    __syncthreads();

    const int node = (blockIdx.x * blockDim.x + t) >> 5;
    const int lane = t & 31;

    if (node < n) {
        const float4* h4 = (const float4*)g_h;
        float dc = g_dinv[node];
        float dc2 = dc * dc;
        int j = g_off[node];
        int end = j + g_deg[node];

        float4 acc = h4[(size_t)node * 32 + lane];
        float4 bv = ((const float4*)b)[lane];
        acc.x = fmaf(acc.x, dc2, bv.x);
        acc.y = fmaf(acc.y, dc2, bv.y);
        acc.z = fmaf(acc.z, dc2, bv.z);
        acc.w = fmaf(acc.w, dc2, bv.w);

        for (; j + 3 < end; j += 4) {
            int r0 = g_src[j], r1 = g_src[j + 1];
            int r2 = g_src[j + 2], r3 = g_src[j + 3];
            float n0 = dc * g_dinv[r0];
            float n1 = dc * g_dinv[r1];
            float n2 = dc * g_dinv[r2];
            float n3 = dc * g_dinv[r3];
            float4 v0 = h4[(size_t)r0 * 32 + lane];
            float4 v1 = h4[(size_t)r1 * 32 + lane];
            float4 v2 = h4[(size_t)r2 * 32 + lane];
            float4 v3 = h4[(size_t)r3 * 32 + lane];
            acc.x = fmaf(v0.x, n0, acc.x); acc.y = fmaf(v0.y, n0, acc.y);
            acc.z = fmaf(v0.z, n0, acc.z); acc.w = fmaf(v0.w, n0, acc.w);
            acc.x = fmaf(v1.x, n1, acc.x); acc.y = fmaf(v1.y, n1, acc.y);
            acc.z = fmaf(v1.z, n1, acc.z); acc.w = fmaf(v1.w, n1, acc.w);
            acc.x = fmaf(v2.x, n2, acc.x); acc.y = fmaf(v2.y, n2, acc.y);
            acc.z = fmaf(v2.z, n2, acc.z); acc.w = fmaf(v2.w, n2, acc.w);
            acc.x = fmaf(v3.x, n3, acc.x); acc.y = fmaf(v3.y, n3, acc.y);
            acc.z = fmaf(v3.z, n3, acc.z); acc.w = fmaf(v3.w, n3, acc.w);
        }
        for (; j < end; j++) {
            int r = g_src[j];
            float nrm = dc * g_dinv[r];
            float4 v = h4[(size_t)r * 32 + lane];
            acc.x = fmaf(v.x, nrm, acc.x);
            acc.y = fmaf(v.y, nrm, acc.y);
            acc.z = fmaf(v.z, nrm, acc.z);
            acc.w = fmaf(v.w, nrm, acc.w);
        }
        acc.x = fmaxf(acc.x, 0.f);
        acc.y = fmaxf(acc.y, 0.f);
        acc.z = fmaxf(acc.z, 0.f);
        acc.w = fmaxf(acc.w, 0.f);
        ((float4*)g_agg)[(size_t)node * 32 + lane] = acc;

        int f0 = lane * 4;
        atomicAdd(&bsum[f0 + 0], acc.x);
        atomicAdd(&bsum[f0 + 1], acc.y);
        atomicAdd(&bsum[f0 + 2], acc.z);
        atomicAdd(&bsum[f0 + 3], acc.w);
        atomicAdd(&bsq[f0 + 0], acc.x * acc.x);
        atomicAdd(&bsq[f0 + 1], acc.y * acc.y);
        atomicAdd(&bsq[f0 + 2], acc.z * acc.z);
        atomicAdd(&bsq[f0 + 3], acc.w * acc.w);
    }
    __syncthreads();
    if (t < F) {
        atomicAdd(&g_sum[t], bsum[t]);
        atomicAdd(&g_sumsq[t], bsq[t]);
    }
}

// ---------------- final: out += relu(agg)*scale + shift (fused BN fold) ----
__global__ void final_kernel(float* __restrict__ out,
                             const float* __restrict__ gamma,
                             const float* __restrict__ beta, int n) {
    __shared__ float ssc[F];
    __shared__ float ssh[F];
    const int t = threadIdx.x;
    if (t < F) {
        float inv_n = 1.f / (float)n;
        float mean = g_sum[t] * inv_n;
        float var = g_sumsq[t] * inv_n - mean * mean;
        float istd = rsqrtf(var + BN_EPS);
        float sc = gamma[t] * istd;
        ssc[t] = sc;
        ssh[t] = beta[t] - mean * sc;
    }
    __syncthreads();

    int tid = blockIdx.x * blockDim.x + t;
    if (tid >= n * (F / 4)) return;
    int s = tid & 31;
    float4 a = ((const float4*)g_agg)[tid];
    float4 sc = *(const float4*)&ssc[s * 4];
    float4 sh = *(const float4*)&ssh[s * 4];
    float4 o = ((float4*)out)[tid];
    o.x += a.x * sc.x + sh.x;
    o.y += a.y * sc.y + sh.y;
    o.z += a.z * sc.z + sh.z;
    o.w += a.w * sc.w + sh.w;
    ((float4*)out)[tid] = o;
}

// ---------------- launch ----------------------------------------------------
static cudaStream_t s_csr = nullptr;
static cudaEvent_t s_evF = nullptr;   // fork after init
static cudaEvent_t s_evC = nullptr;   // conv done (stream 0)
static cudaEvent_t s_evFill = nullptr;// CSR fill done (s_csr)
static cudaEvent_t s_evG1 = nullptr;  // W_res gemm done (s_csr)

extern "C" void kernel_launch(void* const* d_in, const int* in_sizes, int n_in,
                              void* d_out, int out_size) {
    const float* x        = (const float*)d_in[0];
    const void*  ei       = d_in[1];
    const float* W        = (const float*)d_in[2];
    const float* b        = (const float*)d_in[3];
    const float* gamma    = (const float*)d_in[4];
    const float* beta     = (const float*)d_in[5];
    const float* W_res    = (const float*)d_in[6];
    const float* b_res    = (const float*)d_in[7];
    float* out            = (float*)d_out;

    const int n = in_sizes[0] / F;
    const int E = in_sizes[1] / 2;
    const int nb = (n + SCAN_BLK - 1) / SCAN_BLK;

    if (s_csr == nullptr) {   // first (non-captured) call only; reused thereafter
        cudaStreamCreateWithFlags(&s_csr, cudaStreamNonBlocking);
        cudaEventCreateWithFlags(&s_evF, cudaEventDisableTiming);
        cudaEventCreateWithFlags(&s_evC, cudaEventDisableTiming);
        cudaEventCreateWithFlags(&s_evFill, cudaEventDisableTiming);
        cudaEventCreateWithFlags(&s_evG1, cudaEventDisableTiming);
    }

    const int T = 256;
    init_kernel<<<(n + T - 1) / T, T>>>(ei, n);

    // fork CSR branch (needs only init); overlaps conv + gemm0
    cudaEventRecord(s_evF, 0);
    cudaStreamWaitEvent(s_csr, s_evF, 0);
    deg_kernel<<<(E + T - 1) / T, T, 0, s_csr>>>(ei, E);
    scan1_kernel<<<nb, 1024, 0, s_csr>>>(n);
    scan2_kernel<<<1, 32, 0, s_csr>>>(nb);
    scan3_kernel<<<(n + T - 1) / T, T, 0, s_csr>>>(n);
    fill_kernel<<<(E + T - 1) / T, T, 0, s_csr>>>(ei, E);
    cudaEventRecord(s_evFill, s_csr);

    // stream 0: conv, then W-half gemm (critical path to aggregate)
    conv_kernel<<<32 + (n * 32 + T - 1) / T, T>>>(x, W, W_res, n);
    cudaEventRecord(s_evC, 0);
    gemm_mma_kernel<<<(n + GM - 1) / GM, 256>>>(b_res, out, n, 0);

    // s_csr: after conv, W_res-half gemm (overlaps aggregate on stream 0)
    cudaStreamWaitEvent(s_csr, s_evC, 0);
    gemm_mma_kernel<<<(n + GM - 1) / GM, 256, 0, s_csr>>>(b_res, out, n, 1);
    cudaEventRecord(s_evG1, s_csr);

    // aggregate needs g_h (stream 0) + CSR (evFill)
    cudaStreamWaitEvent(0, s_evFill, 0);
    {
        long long work = (long long)n * 32;
        aggregate_kernel<<<(int)((work + T - 1) / T), T>>>(b, n);
    }
    // final needs aggregate (stream 0) + W_res gemm (evG1)
    cudaStreamWaitEvent(0, s_evG1, 0);
    {
        int work = n * (F / 4);
        final_kernel<<<(work + T - 1) / T, T>>>(out, gamma, beta, n);
    }
}